// round 16
// baseline (speedup 1.0000x reference)
#include <cuda_runtime.h>
#include <math.h>

#define Hdim 384
#define Wdim 384
#define HWp  (Hdim*Wdim)
#define BATCH 8
#define PER_IMG (2*Wdim + 2*(Hdim-2))   // 1532 border pixels per image
#define NBORD  (BATCH*PER_IMG)

#define TW 64
#define TH 32
#define HALO_W 68
#define HALO_H 36
#define HALO_N (HALO_W*HALO_H)          // 2448
#define DYN_BYTES (9*HALO_N*4)          // 88128

// Build G[c][di][dj][m] into smem (1296 floats) from the raw params.
__device__ __forceinline__ void build_G(float* sG, int t, int nthr,
                                        const float* __restrict__ bw,
                                        const float* __restrict__ sw,
                                        const float* __restrict__ ss)
{
    for (int idx = t; idx < 16 * 81; idx += nthr) {
        int c = idx / 81, r = idx % 81;
        int di = r / 27, dj = (r / 9) % 3, m = r % 9;
        int k = di * 3 + dj;
        float val;
        if (m == 0) val = bw[c * 9 + k];
        else        val = sw[(c * 9 + k) * 8 + (m - 1)] * ss[c * 9 + k];
        sG[((c * 3 + di) * 3 + dj) * 9 + m] = val;
    }
}

// One composed weight H[cls][m][du*5+dv] from smem G + rw.
__device__ __forceinline__ float compose_H(const float* sG, const float* srw,
                                           int ri, int rj, int m, int du, int dv)
{
    float s0 = 0.f, s1 = 0.f;
    for (int u = 0; u < 3; u++) {
        if (ri == 0 && u == 0) continue;
        if (ri == 2 && u == 2) continue;
        int di = du - u; if (di < 0 || di > 2) continue;
        for (int v = 0; v < 3; v++) {
            if (rj == 0 && v == 0) continue;
            if (rj == 2 && v == 2) continue;
            int dj = dv - v; if (dj < 0 || dj > 2) continue;
#pragma unroll
            for (int c = 0; c < 16; c += 2) {
                s0 = fmaf(srw[(c * 3 + u) * 3 + v],
                          sG[((c * 3 + di) * 3 + dj) * 9 + m], s0);
                s1 = fmaf(srw[((c + 1) * 3 + u) * 3 + v],
                          sG[(((c + 1) * 3 + di) * 3 + dj) * 9 + m], s1);
            }
        }
    }
    return s0 + s1;
}

// ---------------------------------------------------------------------------
// Single fused kernel, grid (12, 6, 9):
//   bz < 8 : interior tile blocks (64x32 tile, 2x4 micro-tile, batch = bz).
//            Edge tiles store scalars, skipping image-ring pixels.
//   bz == 8: 72 border blocks. Compose all 9 Hc classes in own smem, then
//            one ring pixel per thread (features on the fly, Hc from smem).
// No inter-block ordering needed: ring pixels are written ONLY by border
// blocks, all other pixels ONLY by their tile block.
// ---------------------------------------------------------------------------
__global__ void __launch_bounds__(256) main_kernel(const float* __restrict__ x,
                                                   float* __restrict__ out,
                                                   const float* __restrict__ rb,
                                                   const float* __restrict__ bw,
                                                   const float* __restrict__ sw,
                                                   const float* __restrict__ ss,
                                                   const float* __restrict__ rw)
{
    extern __shared__ float dyn[];          // main: sF[9][HALO_N]; border: scratch+Hc
    __shared__ float sH[225];
    __shared__ float sG[16 * 81];
    __shared__ float srw[144];

    int t  = threadIdx.x;

    // ======================= BORDER BLOCKS =======================
    if (blockIdx.z == BATCH) {
        float* bG   = dyn;                  // 1296
        float* brw  = dyn + 1296;           // 144
        float* sHc  = dyn + 1536;           // 9*225 = 2025
        for (int i = t; i < 144; i += 256) brw[i] = rw[i];
        build_G(bG, t, 256, bw, sw, ss);
        __syncthreads();
        for (int idx = t; idx < 9 * 225; idx += 256) {
            int cls = idx / 225, rem = idx % 225;
            int m = rem / 25, r = rem % 25;
            sHc[idx] = compose_H(bG, brw, cls / 3, cls % 3, m, r / 5, r % 5);
        }
        __syncthreads();

        int bid2 = blockIdx.y * gridDim.x + blockIdx.x;   // 0..71
        int pix = bid2 * 256 + t;
        if (pix >= NBORD) return;

        int b = pix / PER_IMG, e = pix % PER_IMG;
        int i, j;
        if (e < Wdim)            { i = 0;        j = e; }
        else if (e < 2 * Wdim)   { i = Hdim - 1; j = e - Wdim; }
        else if (e < 2 * Wdim + (Hdim - 2)) { i = e - 2 * Wdim + 1; j = 0; }
        else                     { i = e - (2 * Wdim + (Hdim - 2)) + 1; j = Wdim - 1; }

        int ri = (i == 0) ? 0 : ((i == Hdim - 1) ? 2 : 1);
        int rj = (j == 0) ? 0 : ((j == Wdim - 1) ? 2 : 1);
        const float* Hc = sHc + (ri * 3 + rj) * 225;
        const float* xp = x + (size_t)b * HWp;

        float acc = 0.f;
#pragma unroll
        for (int du = 0; du < 5; du++) {
            int fy = i + du - 2;
#pragma unroll
            for (int dv = 0; dv < 5; dv++) {
                int fx = j + dv - 2;
                float v = 0.f;
                if (fy >= 0 && fy < Hdim && fx >= 0 && fx < Wdim)
                    v = __ldg(&xp[(size_t)fy * Wdim + fx]);

                int pos = du * 5 + dv;
                float sig = __fdividef(1.0f, 1.0f + __expf(-v));
                acc = fmaf(v * sig, Hc[pos], acc);         // silu plane

                float sc = (v + 2.2f) * 2.5f;
                float tf = floorf(sc);
                int   ti = (int)tf;
                float gt2 = tf * 0.4f - 2.2f;
                float u   = (v - gt2) * 2.5f;
                float u1  = 1.0f - u;
                float u2 = u * u, u12 = u1 * u1;
                const float c6 = 1.0f / 6.0f;
                float w[4];
                w[0] = u12 * u1 * c6;
                w[1] = (3.f*u2*u - 6.f*u2 + 4.f) * c6;
                w[2] = (-3.f*u2*u + 3.f*u2 + 3.f*u + 1.f) * c6;
                w[3] = u2 * u * c6;
                int m0 = ti - 3;
                bool any = (ti >= 0 && ti <= 10);
#pragma unroll
                for (int o = 0; o < 4; o++) {
                    int mo = m0 + o;
                    int mm = min(max(mo, 0), 7);
                    float wo = (any && mo >= 0 && mo <= 7) ? w[o] : 0.f;
                    acc = fmaf(wo, Hc[(mm + 1) * 25 + pos], acc);
                }
            }
        }
        out[(size_t)b * HWp + (size_t)i * Wdim + j] = acc + __ldg(rb);
        return;
    }

    // ======================= INTERIOR TILE BLOCKS =======================
    int tx = t & 15, ty = t >> 4;           // 16 x 16 threads; 2 rows x 4 cols each
    int gx0 = blockIdx.x * TW, gy0 = blockIdx.y * TH;
    int bz = blockIdx.z;
    bool edge_blk = (blockIdx.x == 0) | (blockIdx.x == gridDim.x - 1) |
                    (blockIdx.y == 0) | (blockIdx.y == gridDim.y - 1);

    // --- Prefetch x halo tile into registers (MLP=10) ---
    const float* xp = x + (size_t)bz * HWp;
    float vreg[10];
#pragma unroll
    for (int k = 0; k < 10; k++) {
        int idx = t + k * 256;
        float v = 0.f;
        if (idx < HALO_N) {
            int r = idx / HALO_W, c2 = idx - r * HALO_W;
            int gy = gy0 - 2 + r, gx = gx0 - 2 + c2;
            if (gy >= 0 && gy < Hdim && gx >= 0 && gx < Wdim)
                v = __ldg(&xp[gy * Wdim + gx]);
        }
        vreg[k] = v;
    }

    // --- Stage A1: build G ---
    for (int i = t; i < 144; i += 256) srw[i] = rw[i];
    build_G(sG, t, 256, bw, sw, ss);
    __syncthreads();

    // --- Stage A2: compose interior H; concurrently zero planes 1..8 ---
    float* sF = dyn;
    if (t < 225) {
        int m = t / 25, r = t % 25;
        sH[t] = compose_H(sG, srw, 1, 1, m, r / 5, r % 5);
    }
    {
        float4 z4 = make_float4(0.f, 0.f, 0.f, 0.f);
        float4* zp = (float4*)(sF + HALO_N);
        for (int i = t; i < 8 * HALO_N / 4; i += 256) zp[i] = z4;
    }
    __syncthreads();

    // --- Stage B: features from registers ---
#pragma unroll
    for (int k = 0; k < 10; k++) {
        int idx = t + k * 256;
        if (idx >= HALO_N) break;
        float v = vreg[k];

        float sig = __fdividef(1.0f, 1.0f + __expf(-v));
        sF[idx] = v * sig;

        float sc = (v + 2.2f) * 2.5f;
        float tf = floorf(sc);
        int   ti = (int)tf;
        if (ti >= 0 && ti <= 10) {
            float gt = tf * 0.4f - 2.2f;
            float u  = (v - gt) * 2.5f;
            float u1 = 1.0f - u;
            float u2 = u * u, u12 = u1 * u1;
            const float c6 = 1.0f / 6.0f;
            float w0 = u12 * u1 * c6;
            float w1 = (3.f*u2*u - 6.f*u2 + 4.f) * c6;
            float w2 = (-3.f*u2*u + 3.f*u2 + 3.f*u + 1.f) * c6;
            float w3 = u2 * u * c6;
            int m0 = ti - 3;
            if (m0     >= 0 && m0     <= 7) sF[(m0 + 1) * HALO_N + idx] = w0;
            if (m0 + 1 >= 0 && m0 + 1 <= 7) sF[(m0 + 2) * HALO_N + idx] = w1;
            if (m0 + 2 >= 0 && m0 + 2 <= 7) sF[(m0 + 3) * HALO_N + idx] = w2;
            if (ti     >= 0 && ti     <= 7) sF[(ti + 1) * HALO_N + idx] = w3;
        }
    }
    __syncthreads();

    // --- Stage C: scalar 5x5 conv over 9 planes, 2x4 outputs/thread ---
    float acc[2][4] = {};
#pragma unroll 1
    for (int m = 0; m < 9; m++) {
        const float* Fm = &sF[m * HALO_N];
        float win[6][8];
#pragma unroll
        for (int dy = 0; dy < 6; dy++) {
            const float* row = &Fm[(ty * 2 + dy) * HALO_W + tx * 4];
            float4 a  = *(const float4*)(row);
            float4 bq = *(const float4*)(row + 4);
            win[dy][0] = a.x;  win[dy][1] = a.y;  win[dy][2] = a.z;  win[dy][3] = a.w;
            win[dy][4] = bq.x; win[dy][5] = bq.y; win[dy][6] = bq.z; win[dy][7] = bq.w;
        }
        const float* Hm = &sH[m * 25];
#pragma unroll
        for (int du = 0; du < 5; du++)
#pragma unroll
            for (int dv = 0; dv < 5; dv++) {
                float h = Hm[du * 5 + dv];
#pragma unroll
                for (int ry = 0; ry < 2; ry++)
#pragma unroll
                    for (int rx = 0; rx < 4; rx++)
                        acc[ry][rx] = fmaf(h, win[ry + du][rx + dv], acc[ry][rx]);
            }
    }

    float rbv = __ldg(rb);
    float* op = out + (size_t)bz * HWp;
    if (!edge_blk) {
#pragma unroll
        for (int ry = 0; ry < 2; ry++) {
            int oy = gy0 + ty * 2 + ry;
            float4 o;
            o.x = acc[ry][0] + rbv; o.y = acc[ry][1] + rbv;
            o.z = acc[ry][2] + rbv; o.w = acc[ry][3] + rbv;
            *(float4*)&op[(size_t)oy * Wdim + gx0 + tx * 4] = o;
        }
    } else {
        // Edge tiles: scalar stores, skipping the image ring (owned by border blocks).
#pragma unroll
        for (int ry = 0; ry < 2; ry++) {
            int oy = gy0 + ty * 2 + ry;
            bool yok = (oy > 0) && (oy < Hdim - 1);
#pragma unroll
            for (int rx = 0; rx < 4; rx++) {
                int ox = gx0 + tx * 4 + rx;
                if (yok && ox > 0 && ox < Wdim - 1)
                    op[(size_t)oy * Wdim + ox] = acc[ry][rx] + rbv;
            }
        }
    }
}

// ---------------------------------------------------------------------------
extern "C" void kernel_launch(void* const* d_in, const int* in_sizes, int n_in,
                              void* d_out, int out_size)
{
    const float* x  = (const float*)d_in[0];
    const float* bw = (const float*)d_in[1];
    const float* sw = (const float*)d_in[2];
    const float* ss = (const float*)d_in[3];
    const float* rw = (const float*)d_in[4];
    const float* rb = (const float*)d_in[5];
    float* out = (float*)d_out;

    cudaFuncSetAttribute(main_kernel,
                         cudaFuncAttributeMaxDynamicSharedMemorySize, DYN_BYTES);

    dim3 grid(Wdim / TW, Hdim / TH, BATCH + 1);   // z==BATCH -> border blocks
    main_kernel<<<grid, 256, DYN_BYTES>>>(x, out, rb, bw, sw, ss, rw);
}

// round 17
// speedup vs baseline: 1.2520x; 1.2520x over previous
#include <cuda_runtime.h>
#include <math.h>

#define Hdim 384
#define Wdim 384
#define HWp  (Hdim*Wdim)
#define BATCH 8
#define PER_IMG (2*Wdim + 2*(Hdim-2))   // 1532 border pixels per image
#define NBORD  (BATCH*PER_IMG)

#define TW 64
#define TH 32
#define HALO_W 68
#define HALO_H 36
#define HALO_N (HALO_W*HALO_H)          // 2448
#define DYN_BYTES (9*HALO_N*4)          // 88128

// Composed per-border-class weights, written by main_kernel block (0,0,0),
// consumed by border_kernel (later launch on the same stream).
__device__ float g_Hc[9][225];

// Build G[c][di][dj][m] into smem (1296 floats) from the raw params.
__device__ __forceinline__ void build_G(float* sG, int t, int nthr,
                                        const float* __restrict__ bw,
                                        const float* __restrict__ sw,
                                        const float* __restrict__ ss)
{
    for (int idx = t; idx < 16 * 81; idx += nthr) {
        int c = idx / 81, r = idx % 81;
        int di = r / 27, dj = (r / 9) % 3, m = r % 9;
        int k = di * 3 + dj;
        float val;
        if (m == 0) val = bw[c * 9 + k];
        else        val = sw[(c * 9 + k) * 8 + (m - 1)] * ss[c * 9 + k];
        sG[((c * 3 + di) * 3 + dj) * 9 + m] = val;
    }
}

// One composed weight H[cls][m][du*5+dv] from smem G + rw.
__device__ __forceinline__ float compose_H(const float* sG, const float* srw,
                                           int ri, int rj, int m, int du, int dv)
{
    float s0 = 0.f, s1 = 0.f;
    for (int u = 0; u < 3; u++) {
        if (ri == 0 && u == 0) continue;
        if (ri == 2 && u == 2) continue;
        int di = du - u; if (di < 0 || di > 2) continue;
        for (int v = 0; v < 3; v++) {
            if (rj == 0 && v == 0) continue;
            if (rj == 2 && v == 2) continue;
            int dj = dv - v; if (dj < 0 || dj > 2) continue;
#pragma unroll
            for (int c = 0; c < 16; c += 2) {
                s0 = fmaf(srw[(c * 3 + u) * 3 + v],
                          sG[((c * 3 + di) * 3 + dj) * 9 + m], s0);
                s1 = fmaf(srw[((c + 1) * 3 + u) * 3 + v],
                          sG[(((c + 1) * 3 + di) * 3 + dj) * 9 + m], s1);
            }
        }
    }
    return s0 + s1;
}

// ---------------------------------------------------------------------------
// Kernel 1: fused interior kernel. 256 threads/block (16x16), 64x32 tile,
// 2x4 micro-tile per thread. Dynamic smem 86KB (sF) + static scratch,
// 2 blocks/SM. __launch_bounds__(256, 2): min-blocks hint raises the ptxas
// register budget to 128/thread so the stage-C window stays in registers
// (without it ptxas targets 8 blocks/SM -> 32 regs -> local-memory spills).
// ---------------------------------------------------------------------------
__global__ void __launch_bounds__(256, 2) main_kernel(const float* __restrict__ x,
                                                      float* __restrict__ out,
                                                      const float* __restrict__ rb,
                                                      const float* __restrict__ bw,
                                                      const float* __restrict__ sw,
                                                      const float* __restrict__ ss,
                                                      const float* __restrict__ rw)
{
    extern __shared__ float sF[];           // 9 feature planes [9][HALO_N]
    __shared__ float sH[225];
    __shared__ float sG[16 * 81];
    __shared__ float srw[144];

    int t  = threadIdx.x;
    int tx = t & 15, ty = t >> 4;           // 16 x 16 threads; 2 rows x 4 cols each
    int gx0 = blockIdx.x * TW, gy0 = blockIdx.y * TH;
    int bz = blockIdx.z;

    // --- Prefetch x halo tile into registers (MLP=10, hides LDG latency) ---
    const float* xp = x + (size_t)bz * HWp;
    float vreg[10];
#pragma unroll
    for (int k = 0; k < 10; k++) {
        int idx = t + k * 256;
        float v = 0.f;
        if (idx < HALO_N) {
            int r = idx / HALO_W, c2 = idx - r * HALO_W;
            int gy = gy0 - 2 + r, gx = gx0 - 2 + c2;
            if (gy >= 0 && gy < Hdim && gx >= 0 && gx < Wdim)
                v = __ldg(&xp[gy * Wdim + gx]);
        }
        vreg[k] = v;
    }

    // --- Stage A1: build G ---
    for (int i = t; i < 144; i += 256) srw[i] = rw[i];
    build_G(sG, t, 256, bw, sw, ss);
    __syncthreads();

    // --- Stage A2: compose H; concurrently zero planes 1..8 with float4 ---
    if (t < 225) {
        int m = t / 25, r = t % 25;
        sH[t] = compose_H(sG, srw, 1, 1, m, r / 5, r % 5);
    }
    {
        float4 z4 = make_float4(0.f, 0.f, 0.f, 0.f);
        float4* zp = (float4*)(sF + HALO_N);    // planes 1..8: 8*HALO_N floats
        for (int i = t; i < 8 * HALO_N / 4; i += 256) zp[i] = z4;
    }
    if (blockIdx.x == 0 && blockIdx.y == 0 && bz == 0) {
        for (int idx = t; idx < 9 * 225; idx += 256) {
            int cls = idx / 225, rem = idx % 225;
            int m = rem / 25, r = rem % 25;
            g_Hc[cls][rem] = compose_H(sG, srw, cls / 3, cls % 3, m, r / 5, r % 5);
        }
    }
    __syncthreads();

    // --- Stage B: features from registers (silu store + <=4 scatter) ---
#pragma unroll
    for (int k = 0; k < 10; k++) {
        int idx = t + k * 256;
        if (idx >= HALO_N) break;
        float v = vreg[k];

        float sig = __fdividef(1.0f, 1.0f + __expf(-v));
        sF[idx] = v * sig;

        float sc = (v + 2.2f) * 2.5f;
        float tf = floorf(sc);
        int   ti = (int)tf;
        if (ti >= 0 && ti <= 10) {
            float gt = tf * 0.4f - 2.2f;
            float u  = (v - gt) * 2.5f;
            float u1 = 1.0f - u;
            float u2 = u * u, u12 = u1 * u1;
            const float c6 = 1.0f / 6.0f;
            float w0 = u12 * u1 * c6;
            float w1 = (3.f*u2*u - 6.f*u2 + 4.f) * c6;
            float w2 = (-3.f*u2*u + 3.f*u2 + 3.f*u + 1.f) * c6;
            float w3 = u2 * u * c6;
            int m0 = ti - 3;
            if (m0     >= 0 && m0     <= 7) sF[(m0 + 1) * HALO_N + idx] = w0;
            if (m0 + 1 >= 0 && m0 + 1 <= 7) sF[(m0 + 2) * HALO_N + idx] = w1;
            if (m0 + 2 >= 0 && m0 + 2 <= 7) sF[(m0 + 3) * HALO_N + idx] = w2;
            if (ti     >= 0 && ti     <= 7) sF[(ti + 1) * HALO_N + idx] = w3;
        }
    }
    __syncthreads();

    // --- Stage C: scalar 5x5 conv over 9 planes, 2x4 outputs/thread ---
    float acc[2][4] = {};
#pragma unroll 1
    for (int m = 0; m < 9; m++) {
        const float* Fm = &sF[m * HALO_N];
        float win[6][8];
#pragma unroll
        for (int dy = 0; dy < 6; dy++) {
            const float* row = &Fm[(ty * 2 + dy) * HALO_W + tx * 4];
            float4 a  = *(const float4*)(row);
            float4 bq = *(const float4*)(row + 4);
            win[dy][0] = a.x;  win[dy][1] = a.y;  win[dy][2] = a.z;  win[dy][3] = a.w;
            win[dy][4] = bq.x; win[dy][5] = bq.y; win[dy][6] = bq.z; win[dy][7] = bq.w;
        }
        const float* Hm = &sH[m * 25];
#pragma unroll
        for (int du = 0; du < 5; du++)
#pragma unroll
            for (int dv = 0; dv < 5; dv++) {
                float h = Hm[du * 5 + dv];
#pragma unroll
                for (int ry = 0; ry < 2; ry++)
#pragma unroll
                    for (int rx = 0; rx < 4; rx++)
                        acc[ry][rx] = fmaf(h, win[ry + du][rx + dv], acc[ry][rx]);
            }
    }

    float rbv = __ldg(rb);
    float* op = out + (size_t)bz * HWp;
#pragma unroll
    for (int ry = 0; ry < 2; ry++) {
        int oy = gy0 + ty * 2 + ry;
        float4 o;
        o.x = acc[ry][0] + rbv; o.y = acc[ry][1] + rbv;
        o.z = acc[ry][2] + rbv; o.w = acc[ry][3] + rbv;
        *(float4*)&op[(size_t)oy * Wdim + gx0 + tx * 4] = o;
    }
}

// ---------------------------------------------------------------------------
// Kernel 2: border ring, ONE WARP PER PIXEL. Lanes 0..24 each handle one
// (du,dv) tap; clamped unconditional H loads (MLP=4); shfl reduce.
// ---------------------------------------------------------------------------
__global__ void __launch_bounds__(256) border_kernel(const float* __restrict__ x,
                                                     float* __restrict__ out,
                                                     const float* __restrict__ rb)
{
    int gt   = blockIdx.x * 256 + threadIdx.x;
    int warp = gt >> 5;
    int lane = gt & 31;
    if (warp >= NBORD) return;

    int b = warp / PER_IMG, e = warp % PER_IMG;
    int i, j;
    if (e < Wdim)            { i = 0;        j = e; }
    else if (e < 2 * Wdim)   { i = Hdim - 1; j = e - Wdim; }
    else if (e < 2 * Wdim + (Hdim - 2)) { i = e - 2 * Wdim + 1; j = 0; }
    else                     { i = e - (2 * Wdim + (Hdim - 2)) + 1; j = Wdim - 1; }

    int ri = (i == 0) ? 0 : ((i == Hdim - 1) ? 2 : 1);
    int rj = (j == 0) ? 0 : ((j == Wdim - 1) ? 2 : 1);
    const float* Hc = g_Hc[ri * 3 + rj];

    float acc = 0.f;
    if (lane < 25) {
        int du = lane / 5, dv = lane - du * 5;
        int fy = i + du - 2, fx = j + dv - 2;
        float v = 0.f;
        if (fy >= 0 && fy < Hdim && fx >= 0 && fx < Wdim)
            v = __ldg(&x[(size_t)b * HWp + (size_t)fy * Wdim + fx]);

        float h0 = __ldg(&Hc[lane]);               // silu-plane weight
        float sig = __fdividef(1.0f, 1.0f + __expf(-v));

        float sc = (v + 2.2f) * 2.5f;
        float tf = floorf(sc);
        int   ti = (int)tf;
        float gt2 = tf * 0.4f - 2.2f;
        float u   = (v - gt2) * 2.5f;
        float u1  = 1.0f - u;
        float u2 = u * u, u12 = u1 * u1;
        const float c6 = 1.0f / 6.0f;
        float w[4];
        w[0] = u12 * u1 * c6;
        w[1] = (3.f*u2*u - 6.f*u2 + 4.f) * c6;
        w[2] = (-3.f*u2*u + 3.f*u2 + 3.f*u + 1.f) * c6;
        w[3] = u2 * u * c6;
        int m0 = ti - 3;
        bool any = (ti >= 0 && ti <= 10);
        float hv[4];
#pragma unroll
        for (int o = 0; o < 4; o++) {
            int mm = min(max(m0 + o, 0), 7);
            hv[o] = __ldg(&Hc[(mm + 1) * 25 + lane]);
        }
        acc = (v * sig) * h0;
#pragma unroll
        for (int o = 0; o < 4; o++) {
            int mo = m0 + o;
            float wo = (any && mo >= 0 && mo <= 7) ? w[o] : 0.f;
            acc = fmaf(wo, hv[o], acc);
        }
    }
#pragma unroll
    for (int off = 16; off >= 1; off >>= 1)
        acc += __shfl_xor_sync(0xffffffffu, acc, off);

    if (lane == 0)
        out[(size_t)b * HWp + (size_t)i * Wdim + j] = acc + __ldg(rb);
}

// ---------------------------------------------------------------------------
extern "C" void kernel_launch(void* const* d_in, const int* in_sizes, int n_in,
                              void* d_out, int out_size)
{
    const float* x  = (const float*)d_in[0];
    const float* bw = (const float*)d_in[1];
    const float* sw = (const float*)d_in[2];
    const float* ss = (const float*)d_in[3];
    const float* rw = (const float*)d_in[4];
    const float* rb = (const float*)d_in[5];
    float* out = (float*)d_out;

    cudaFuncSetAttribute(main_kernel,
                         cudaFuncAttributeMaxDynamicSharedMemorySize, DYN_BYTES);

    dim3 grid(Wdim / TW, Hdim / TH, BATCH);
    main_kernel<<<grid, 256, DYN_BYTES>>>(x, out, rb, bw, sw, ss, rw);
    int nthreads = NBORD * 32;               // one warp per border pixel
    border_kernel<<<(nthreads + 255) / 256, 256>>>(x, out, rb);
}